// round 8
// baseline (speedup 1.0000x reference)
#include <cuda_runtime.h>
#include <cuda_bf16.h>
#include <cstdint>

#define EPS 0.0001f
#define N_DIFFS 4194304
#define ROWS_PER_CTA 1024                      // 256 threads * 4 rows
#define IDX_INTS_PER_CTA (ROWS_PER_CTA * 3)    // 3072 ints = 12288 B
#define IDX_BYTES_PER_CTA (IDX_INTS_PER_CTA * 4)
#define OUT_BYTES_PER_CTA (ROWS_PER_CTA * 4)   // 4096 B

__device__ __forceinline__ uint32_t smem_u32(const void* p) {
    uint32_t a;
    asm("{ .reg .u64 t; cvta.to.shared.u64 t, %1; cvt.u32.u64 %0, t; }" : "=r"(a) : "l"(p));
    return a;
}

__global__ void __launch_bounds__(256)
perf_model_kernel(const float* __restrict__ bin_centers,
                  const int*   __restrict__ obs_idx,
                  const float* __restrict__ lb1p,
                  const float* __restrict__ ub1p,
                  const float* __restrict__ lb2p,
                  const float* __restrict__ ub2p,
                  const float* __restrict__ respp,
                  float* __restrict__ out)
{
    __shared__ alignas(128) int   s_idx[IDX_INTS_PER_CTA];
    __shared__ alignas(128) float s_out[ROWS_PER_CTA];
    __shared__ alignas(8) uint64_t s_mbar;

    int tid = threadIdx.x;
    uint32_t mbar = smem_u32(&s_mbar);

    if (tid == 0) {
        asm volatile("mbarrier.init.shared.b64 [%0], 1;" :: "r"(mbar) : "memory");
    }
    __syncthreads();

    if (tid == 0) {
        asm volatile("mbarrier.arrive.expect_tx.shared.b64 _, [%0], %1;"
                     :: "r"(mbar), "r"((uint32_t)IDX_BYTES_PER_CTA) : "memory");
        const char* src = reinterpret_cast<const char*>(obs_idx)
                        + (long long)blockIdx.x * IDX_BYTES_PER_CTA;
        asm volatile("cp.async.bulk.shared::cluster.global.mbarrier::complete_tx::bytes "
                     "[%0], [%1], %2, [%3];"
                     :: "r"(smem_u32(s_idx)), "l"(src),
                        "r"((uint32_t)IDX_BYTES_PER_CTA), "r"(mbar) : "memory");
    }

    // uniform scalar prep — overlaps the TMA transfer
    float a1 = __ldg(lb1p), b1 = __ldg(ub1p);
    float a2 = __ldg(lb2p), b2 = __ldg(ub2p);
    float nlb1 = __frcp_rn(1.0f + __expf(-fminf(a1, b1)));
    float nub1 = __frcp_rn(1.0f + __expf(-fmaxf(a1, b1)));
    float nlb2 = __frcp_rn(1.0f + __expf(-fminf(a2, b2)));
    float nub2 = __frcp_rn(1.0f + __expf(-fmaxf(a2, b2)));
    float r    = __frcp_rn(1.0f + __expf(-__ldg(respp)));
    float inv1 = __frcp_rn(nub1 - nlb1 + EPS);
    float inv2 = __frcp_rn(nub2 - nlb2 + EPS);
    float c1 = nub1 * inv1;
    float c2 = nub2 * inv2;

    // wait for the idx tile (parity 0, single phase per launch)
    {
        uint32_t done;
        asm volatile(
            "{\n\t"
            ".reg .pred p;\n\t"
            "mbarrier.try_wait.parity.shared.b64 p, [%1], 0;\n\t"
            "selp.b32 %0, 1, 0, p;\n\t"
            "}" : "=r"(done) : "r"(mbar) : "memory");
        while (!done) {
            asm volatile(
                "{\n\t"
                ".reg .pred p;\n\t"
                "mbarrier.try_wait.parity.shared.b64 p, [%1], 0, 0x989680;\n\t"
                "selp.b32 %0, 1, 0, p;\n\t"
                "}" : "=r"(done) : "r"(mbar) : "memory");
        }
    }

    // this thread's 12 indices: 3x LDS.128, conflict-free
    const int4* sp = reinterpret_cast<const int4*>(s_idx) + tid * 3;
    int4 v0 = sp[0];
    int4 v1 = sp[1];
    int4 v2 = sp[2];

    // gathers from the L1-resident 4KB table
    float x0a = __ldg(bin_centers + v0.x), x0b = __ldg(bin_centers + v0.y);
    float x1a = __ldg(bin_centers + v0.w), x1b = __ldg(bin_centers + v1.x);
    float x2a = __ldg(bin_centers + v1.z), x2b = __ldg(bin_centers + v1.w);
    float x3a = __ldg(bin_centers + v2.y), x3b = __ldg(bin_centers + v2.z);

    // perf factor = saturate((ub - x) * inv) = saturate(fma(-x, inv, ub*inv))
    float4 o;
    o.x = __saturatef(fmaf(-x0a, inv1, c1)) * __saturatef(fmaf(-x0b, inv2, c2)) * r;
    o.y = __saturatef(fmaf(-x1a, inv1, c1)) * __saturatef(fmaf(-x1b, inv2, c2)) * r;
    o.z = __saturatef(fmaf(-x2a, inv1, c1)) * __saturatef(fmaf(-x2b, inv2, c2)) * r;
    o.w = __saturatef(fmaf(-x3a, inv1, c1)) * __saturatef(fmaf(-x3b, inv2, c2)) * r;

    // stage output in smem (STS.128, conflict-free), then bulk-store S->G
    reinterpret_cast<float4*>(s_out)[tid] = o;
    __syncthreads();

    if (tid == 0) {
        asm volatile("fence.proxy.async.shared::cta;" ::: "memory");
        char* dst = reinterpret_cast<char*>(out)
                  + (long long)blockIdx.x * OUT_BYTES_PER_CTA;
        asm volatile("cp.async.bulk.global.shared::cta.bulk_group [%0], [%1], %2;"
                     :: "l"(dst), "r"(smem_u32(s_out)),
                        "r"((uint32_t)OUT_BYTES_PER_CTA) : "memory");
        asm volatile("cp.async.bulk.commit_group;" ::: "memory");
        asm volatile("cp.async.bulk.wait_group 0;" ::: "memory");
    }
}

extern "C" void kernel_launch(void* const* d_in, const int* in_sizes, int n_in,
                              void* d_out, int out_size)
{
    // metadata order: bin_centers, obs_idx, lb1, ub1, lb2, ub2, resp
    const float* bin_centers = (const float*)d_in[0];
    const int*   obs_idx     = (const int*)  d_in[1];
    const float* lb1         = (const float*)d_in[2];
    const float* ub1         = (const float*)d_in[3];
    const float* lb2         = (const float*)d_in[4];
    const float* ub2         = (const float*)d_in[5];
    const float* resp        = (const float*)d_in[6];
    float* out = (float*)d_out;

    const int threads = 256;
    const int blocks = N_DIFFS / ROWS_PER_CTA;   // 4096

    perf_model_kernel<<<blocks, threads>>>(bin_centers, obs_idx,
                                           lb1, ub1, lb2, ub2, resp, out);
}

// round 9
// speedup vs baseline: 1.0984x; 1.0984x over previous
#include <cuda_runtime.h>
#include <cstdint>

#define EPS 0.0001f
#define N_DIFFS 4194304
#define THREADS 256
#define ROWS_PER_TILE 512                       // 2 rows per thread per tile
#define TILE_INTS (ROWS_PER_TILE * 3)           // 1536 ints = 6144 B
#define TILE_BYTES (TILE_INTS * 4)
#define TILES_PER_CTA 4
#define ROWS_PER_CTA (ROWS_PER_TILE * TILES_PER_CTA)   // 2048

__device__ __forceinline__ uint32_t smem_u32(const void* p) {
    uint32_t a;
    asm("{ .reg .u64 t; cvta.to.shared.u64 t, %1; cvt.u32.u64 %0, t; }" : "=r"(a) : "l"(p));
    return a;
}

__device__ __forceinline__ void mbar_wait0(uint32_t mbar) {
    uint32_t done;
    asm volatile(
        "{\n\t"
        ".reg .pred p;\n\t"
        "mbarrier.try_wait.parity.shared.b64 p, [%1], 0;\n\t"
        "selp.b32 %0, 1, 0, p;\n\t"
        "}" : "=r"(done) : "r"(mbar) : "memory");
    while (!done) {
        asm volatile(
            "{\n\t"
            ".reg .pred p;\n\t"
            "mbarrier.try_wait.parity.shared.b64 p, [%1], 0, 0x989680;\n\t"
            "selp.b32 %0, 1, 0, p;\n\t"
            "}" : "=r"(done) : "r"(mbar) : "memory");
    }
}

__global__ void __launch_bounds__(THREADS)
perf_model_kernel(const float* __restrict__ bin_centers,
                  const int*   __restrict__ obs_idx,
                  const float* __restrict__ lb1p,
                  const float* __restrict__ ub1p,
                  const float* __restrict__ lb2p,
                  const float* __restrict__ ub2p,
                  const float* __restrict__ respp,
                  float* __restrict__ out)
{
    __shared__ alignas(128) int s_idx[TILES_PER_CTA][TILE_INTS];
    __shared__ alignas(8) uint64_t s_mbar[TILES_PER_CTA];

    int tid = threadIdx.x;

    if (tid == 0) {
        #pragma unroll
        for (int s = 0; s < TILES_PER_CTA; s++)
            asm volatile("mbarrier.init.shared.b64 [%0], 1;"
                         :: "r"(smem_u32(&s_mbar[s])) : "memory");
    }
    __syncthreads();   // the ONLY barrier — before any TMA touches the mbars

    if (tid == 0) {
        const char* src0 = reinterpret_cast<const char*>(obs_idx)
                         + (long long)blockIdx.x * (TILES_PER_CTA * TILE_BYTES);
        #pragma unroll
        for (int s = 0; s < TILES_PER_CTA; s++) {
            uint32_t mb = smem_u32(&s_mbar[s]);
            asm volatile("mbarrier.arrive.expect_tx.shared.b64 _, [%0], %1;"
                         :: "r"(mb), "r"((uint32_t)TILE_BYTES) : "memory");
            asm volatile("cp.async.bulk.shared::cluster.global.mbarrier::complete_tx::bytes "
                         "[%0], [%1], %2, [%3];"
                         :: "r"(smem_u32(&s_idx[s][0])),
                            "l"(src0 + (long long)s * TILE_BYTES),
                            "r"((uint32_t)TILE_BYTES), "r"(mb) : "memory");
        }
    }

    // uniform scalar prep — overlaps the transfers
    float a1 = __ldg(lb1p), b1 = __ldg(ub1p);
    float a2 = __ldg(lb2p), b2 = __ldg(ub2p);
    float nlb1 = __frcp_rn(1.0f + __expf(-fminf(a1, b1)));
    float nub1 = __frcp_rn(1.0f + __expf(-fmaxf(a1, b1)));
    float nlb2 = __frcp_rn(1.0f + __expf(-fminf(a2, b2)));
    float nub2 = __frcp_rn(1.0f + __expf(-fmaxf(a2, b2)));
    float r    = __frcp_rn(1.0f + __expf(-__ldg(respp)));
    float inv1 = __frcp_rn(nub1 - nlb1 + EPS);
    float inv2 = __frcp_rn(nub2 - nlb2 + EPS);
    float c1 = nub1 * inv1;
    float c2 = nub2 * inv2;

    long long cta_row0 = (long long)blockIdx.x * ROWS_PER_CTA;

    #pragma unroll
    for (int s = 0; s < TILES_PER_CTA; s++) {
        mbar_wait0(smem_u32(&s_mbar[s]));

        // this thread's 2 rows in tile s: 6 ints at s_idx[s][6*tid], 8B-aligned
        const int2* sp = reinterpret_cast<const int2*>(&s_idx[s][0]) + tid * 3;
        int2 w0 = sp[0];   // row A: e0, e1
        int2 w1 = sp[1];   // e2 (unused), row B e0
        int2 w2 = sp[2];   // row B e1, e2 (unused)

        float xa1 = __ldg(bin_centers + w0.x);
        float xa2 = __ldg(bin_centers + w0.y);
        float xb1 = __ldg(bin_centers + w1.y);
        float xb2 = __ldg(bin_centers + w2.x);

        float2 o;
        o.x = __saturatef(fmaf(-xa1, inv1, c1)) * __saturatef(fmaf(-xa2, inv2, c2)) * r;
        o.y = __saturatef(fmaf(-xb1, inv1, c1)) * __saturatef(fmaf(-xb2, inv2, c2)) * r;

        long long row = cta_row0 + (long long)s * ROWS_PER_TILE + 2 * tid;
        *reinterpret_cast<float2*>(out + row) = o;
    }
}

extern "C" void kernel_launch(void* const* d_in, const int* in_sizes, int n_in,
                              void* d_out, int out_size)
{
    // metadata order: bin_centers, obs_idx, lb1, ub1, lb2, ub2, resp
    const float* bin_centers = (const float*)d_in[0];
    const int*   obs_idx     = (const int*)  d_in[1];
    const float* lb1         = (const float*)d_in[2];
    const float* ub1         = (const float*)d_in[3];
    const float* lb2         = (const float*)d_in[4];
    const float* ub2         = (const float*)d_in[5];
    const float* resp        = (const float*)d_in[6];
    float* out = (float*)d_out;

    const int blocks = N_DIFFS / ROWS_PER_CTA;   // 2048

    perf_model_kernel<<<blocks, THREADS>>>(bin_centers, obs_idx,
                                           lb1, ub1, lb2, ub2, resp, out);
}

// round 10
// speedup vs baseline: 1.1577x; 1.0540x over previous
#include <cuda_runtime.h>
#include <cstdint>

#define EPS 0.0001f
#define N_DIFFS 4194304
#define N_BINS 1000
#define THREADS 256
#define ROWS_PER_CTA 1024                      // 4 rows per thread
#define IDX_INTS_PER_CTA (ROWS_PER_CTA * 3)    // 3072 ints = 12288 B
#define IDX_BYTES_PER_CTA (IDX_INTS_PER_CTA * 4)

__device__ __forceinline__ uint32_t smem_u32(const void* p) {
    uint32_t a;
    asm("{ .reg .u64 t; cvta.to.shared.u64 t, %1; cvt.u32.u64 %0, t; }" : "=r"(a) : "l"(p));
    return a;
}

__device__ __forceinline__ void mbar_wait0(uint32_t mbar) {
    uint32_t done;
    asm volatile(
        "{\n\t"
        ".reg .pred p;\n\t"
        "mbarrier.try_wait.parity.shared.b64 p, [%1], 0;\n\t"
        "selp.b32 %0, 1, 0, p;\n\t"
        "}" : "=r"(done) : "r"(mbar) : "memory");
    while (!done) {
        asm volatile(
            "{\n\t"
            ".reg .pred p;\n\t"
            "mbarrier.try_wait.parity.shared.b64 p, [%1], 0, 0x989680;\n\t"
            "selp.b32 %0, 1, 0, p;\n\t"
            "}" : "=r"(done) : "r"(mbar) : "memory");
    }
}

__global__ void __launch_bounds__(THREADS)
perf_model_kernel(const float* __restrict__ bin_centers,
                  const int*   __restrict__ obs_idx,
                  const float* __restrict__ lb1p,
                  const float* __restrict__ ub1p,
                  const float* __restrict__ lb2p,
                  const float* __restrict__ ub2p,
                  const float* __restrict__ respp,
                  float* __restrict__ out)
{
    __shared__ alignas(128) int   s_idx[IDX_INTS_PER_CTA];
    __shared__ alignas(128) float s_bc[N_BINS];
    __shared__ alignas(8) uint64_t s_mbar;

    int tid = threadIdx.x;
    uint32_t mbar = smem_u32(&s_mbar);

    if (tid == 0) {
        asm volatile("mbarrier.init.shared.b64 [%0], 1;" :: "r"(mbar) : "memory");
    }
    __syncthreads();

    // launch the 12 KB bulk copy immediately (flies while we fill the table)
    if (tid == 0) {
        asm volatile("mbarrier.arrive.expect_tx.shared.b64 _, [%0], %1;"
                     :: "r"(mbar), "r"((uint32_t)IDX_BYTES_PER_CTA) : "memory");
        const char* src = reinterpret_cast<const char*>(obs_idx)
                        + (long long)blockIdx.x * IDX_BYTES_PER_CTA;
        asm volatile("cp.async.bulk.shared::cluster.global.mbarrier::complete_tx::bytes "
                     "[%0], [%1], %2, [%3];"
                     :: "r"(smem_u32(s_idx)), "l"(src),
                        "r"((uint32_t)IDX_BYTES_PER_CTA), "r"(mbar) : "memory");
    }

    // cooperative 4 KB table fill — L2-hit LDGs, overlapped with the TMA
    for (int i = tid; i < N_BINS; i += THREADS)
        s_bc[i] = __ldg(bin_centers + i);

    // uniform scalar prep (also overlapped)
    float a1 = __ldg(lb1p), b1 = __ldg(ub1p);
    float a2 = __ldg(lb2p), b2 = __ldg(ub2p);
    float nlb1 = __frcp_rn(1.0f + __expf(-fminf(a1, b1)));
    float nub1 = __frcp_rn(1.0f + __expf(-fmaxf(a1, b1)));
    float nlb2 = __frcp_rn(1.0f + __expf(-fminf(a2, b2)));
    float nub2 = __frcp_rn(1.0f + __expf(-fmaxf(a2, b2)));
    float r    = __frcp_rn(1.0f + __expf(-__ldg(respp)));
    float inv1 = __frcp_rn(nub1 - nlb1 + EPS);
    float inv2 = __frcp_rn(nub2 - nlb2 + EPS);
    float c1 = nub1 * inv1;
    float c2 = nub2 * inv2;

    __syncthreads();          // table visible (cost hidden under TMA flight)
    mbar_wait0(mbar);         // idx tile ready

    // this thread's 12 indices: 3x LDS.128, conflict-free phase pattern
    const int4* sp = reinterpret_cast<const int4*>(s_idx) + tid * 3;
    int4 v0 = sp[0];
    int4 v1 = sp[1];
    int4 v2 = sp[2];

    // gathers from the shared-memory table (crossbar, no L1tex replay)
    float x0a = s_bc[v0.x], x0b = s_bc[v0.y];
    float x1a = s_bc[v0.w], x1b = s_bc[v1.x];
    float x2a = s_bc[v1.z], x2b = s_bc[v1.w];
    float x3a = s_bc[v2.y], x3b = s_bc[v2.z];

    // perf factor = saturate((ub - x) * inv) = saturate(fma(-x, inv, ub*inv))
    float4 o;
    o.x = __saturatef(fmaf(-x0a, inv1, c1)) * __saturatef(fmaf(-x0b, inv2, c2)) * r;
    o.y = __saturatef(fmaf(-x1a, inv1, c1)) * __saturatef(fmaf(-x1b, inv2, c2)) * r;
    o.z = __saturatef(fmaf(-x2a, inv1, c1)) * __saturatef(fmaf(-x2b, inv2, c2)) * r;
    o.w = __saturatef(fmaf(-x3a, inv1, c1)) * __saturatef(fmaf(-x3b, inv2, c2)) * r;

    long long task = (long long)blockIdx.x * THREADS + tid;
    reinterpret_cast<float4*>(out)[task] = o;
}

extern "C" void kernel_launch(void* const* d_in, const int* in_sizes, int n_in,
                              void* d_out, int out_size)
{
    // metadata order: bin_centers, obs_idx, lb1, ub1, lb2, ub2, resp
    const float* bin_centers = (const float*)d_in[0];
    const int*   obs_idx     = (const int*)  d_in[1];
    const float* lb1         = (const float*)d_in[2];
    const float* ub1         = (const float*)d_in[3];
    const float* lb2         = (const float*)d_in[4];
    const float* ub2         = (const float*)d_in[5];
    const float* resp        = (const float*)d_in[6];
    float* out = (float*)d_out;

    const int blocks = N_DIFFS / ROWS_PER_CTA;   // 4096

    perf_model_kernel<<<blocks, THREADS>>>(bin_centers, obs_idx,
                                           lb1, ub1, lb2, ub2, resp, out);
}